// round 13
// baseline (speedup 1.0000x reference)
#include <cuda_runtime.h>
#include <cuda_bf16.h>
#include <math.h>

#define Nn 8192
#define IN_F 256
#define OUT_F 128
#define NWORDS 256   // bitmap words per row (8192 bits)
#define CAPW 256     // per-warp neighbor list capacity (expected degree ~32)

// ---------------- device scratch (no allocs allowed) ----------------
// g_adj and g_vs start zeroed (static init) and are re-zeroed by k_attn
// after use, so every replay starts from a clean state.
__device__ float    g_hc[Nn * OUT_F];          // 4 MB
__device__ unsigned g_adj[Nn * NWORDS];        // 8 MB adjacency bitmap
__device__ float    g_sc_src[Nn];
__device__ float    g_ss_src[Nn];
__device__ float2   g_sd[Nn];                  // (sc_dst, ss_dst) packed
__device__ float    g_vs1[IN_F], g_vs2[IN_F];  // hs-GEMM fold vectors
__device__ float    g_scal[4];                 // ca, cs, bs1, bs2

__device__ __forceinline__ float lrelu(float x) { return x > 0.f ? x : 0.01f * x; }

__device__ __forceinline__ float warpMax(float v) {
    #pragma unroll
    for (int o = 16; o; o >>= 1) v = fmaxf(v, __shfl_xor_sync(0xffffffffu, v, o));
    return v;
}
__device__ __forceinline__ float warpSum(float v) {
    #pragma unroll
    for (int o = 16; o; o >>= 1) v += __shfl_xor_sync(0xffffffffu, v, o);
    return v;
}

// ---------------- kernels ----------------
// Edge bitmap build: all 4 candidate loads (both int32/int64 interpretations)
// issued BEFORE the detection barrier -> MLP=4, no dependent post-barrier load.
// Blocks 0..7 also accumulate the hs-GEMM fold into g_vs; block 8 does bias
// dots + coefficient abs.
__global__ void k_edges(const int* __restrict__ p32, int E,
                        const float* __restrict__ Ws_w,
                        const float* __restrict__ Ws_b,
                        const float* __restrict__ as_w,
                        const float* __restrict__ Ws_coff,
                        const float* __restrict__ Wc_coff) {
    int tid = threadIdx.x;
    int e = blockIdx.x * blockDim.x + tid;
    const long long* p64 = (const long long*)p32;

    unsigned long long vr = 0ull, vc = 0ull;
    int r32 = 0, c32 = 0;
    if (e < E) {
        vr  = (unsigned long long)p64[e];       // i64 row candidate
        vc  = (unsigned long long)p64[E + e];   // i64 col candidate
        r32 = p32[e];                           // i32 row candidate
        c32 = p32[E + e];                       // i32 col candidate
    }
    // int64 little-endian ids < 8192 -> high words all zero.
    int hiw = (((vr | vc) >> 32) != 0ull);
    int isi32 = __syncthreads_or(hiw);
    if (e < E) {
        int r = isi32 ? r32 : (int)(unsigned)vr;
        int c = isi32 ? c32 : (int)(unsigned)vc;
        if ((unsigned)r < Nn && (unsigned)c < Nn)
            atomicOr(&g_adj[r * NWORDS + (c >> 5)], 1u << (c & 31));
    }
    if (blockIdx.x < 8) {
        float v1 = 0.f, v2 = 0.f;
        #pragma unroll
        for (int i = 0; i < 16; i++) {
            int f = blockIdx.x * 16 + i;
            float w = Ws_w[f * IN_F + tid];
            v1 += w * as_w[f];
            v2 += w * as_w[OUT_F + f];
        }
        atomicAdd(&g_vs1[tid], v1);
        atomicAdd(&g_vs2[tid], v2);
    } else if (blockIdx.x == 8 && tid < 32) {
        float b1 = 0.f, b2 = 0.f;
        #pragma unroll
        for (int i = 0; i < 4; i++) {
            int f = tid + 32 * i;
            float wb = Ws_b[f];
            b1 += wb * as_w[f];
            b2 += wb * as_w[OUT_F + f];
        }
        b1 = warpSum(b1);
        b2 = warpSum(b2);
        if (tid == 0) {
            g_scal[0] = fabsf(Ws_coff[0]);  // multiplies alpha_c
            g_scal[1] = fabsf(Wc_coff[0]);  // multiplies alpha_s
            g_scal[2] = b1;
            g_scal[3] = b2;
        }
    }
}

// ---------------- split-bf16 tensor-core GEMM + fused structure scores -----
// hc = h_context @ Wc_w^T + Wc_b via mma.sync m16n8k16 bf16:
//   a*b ~= a_hi*b_hi + a_hi*b_lo + a_lo*b_hi   (fp32 accumulate)
#define BM 32
#define BK 32
#define KCHUNKS (IN_F / BK)
#define APAD 40

__device__ __forceinline__ void mma_bf16(float* c, const unsigned* a,
                                         unsigned b0, unsigned b1) {
    asm volatile(
        "mma.sync.aligned.m16n8k16.row.col.f32.bf16.bf16.f32 "
        "{%0,%1,%2,%3}, {%4,%5,%6,%7}, {%8,%9}, {%0,%1,%2,%3};"
        : "+f"(c[0]), "+f"(c[1]), "+f"(c[2]), "+f"(c[3])
        : "r"(a[0]), "r"(a[1]), "r"(a[2]), "r"(a[3]), "r"(b0), "r"(b1));
}

__device__ __forceinline__ unsigned pk2(float x, float y) {
    unsigned r;
    asm("cvt.rn.bf16x2.f32 %0, %1, %2;" : "=r"(r) : "f"(y), "f"(x));
    return r;
}
__device__ __forceinline__ float bflo(unsigned u) { return __uint_as_float(u << 16); }
__device__ __forceinline__ float bfhi(unsigned u) { return __uint_as_float(u & 0xffff0000u); }

__device__ __forceinline__ void conv_sts(float4 v, __nv_bfloat16* hip, __nv_bfloat16* lop) {
    unsigned h0 = pk2(v.x, v.y);
    unsigned h1 = pk2(v.z, v.w);
    unsigned l0 = pk2(v.x - bflo(h0), v.y - bfhi(h0));
    unsigned l1 = pk2(v.z - bflo(h1), v.w - bfhi(h1));
    *(uint2*)hip = make_uint2(h0, h1);
    *(uint2*)lop = make_uint2(l0, l1);
}

__global__ void __launch_bounds__(256, 2) k_gemm(const float* __restrict__ A,
                                                 const float* __restrict__ W,
                                                 const float* __restrict__ b,
                                                 const float* __restrict__ ac_w,
                                                 const float* __restrict__ hstruct) {
    __shared__ __align__(16) __nv_bfloat16 A_s[2][2][BM][APAD];
    __shared__ __align__(16) __nv_bfloat16 W_s[2][2][OUT_F][APAD];
    __shared__ float p_s1[8][16], p_s2[8][16];

    int tid = threadIdx.x;
    int lane = tid & 31;
    int warp = tid >> 5;
    int block_m = blockIdx.x * BM;

    int arow = tid >> 3;             // 0..31
    int akc  = (tid & 7) * 4;

    float4 ra0, rw0, rw1, rw2, rw3;
    #define GLD(c0_)                                                          \
        ra0 = *(const float4*)&A[(size_t)(block_m + arow) * IN_F + (c0_) + akc];      \
        rw0 = *(const float4*)&W[(size_t)arow * IN_F + (c0_) + akc];                  \
        rw1 = *(const float4*)&W[(size_t)(arow + 32) * IN_F + (c0_) + akc];           \
        rw2 = *(const float4*)&W[(size_t)(arow + 64) * IN_F + (c0_) + akc];           \
        rw3 = *(const float4*)&W[(size_t)(arow + 96) * IN_F + (c0_) + akc];

    // prefetch first GEMM tile BEFORE the sscore prologue (loads in flight
    // during the ~2us of softmax compute below)
    GLD(0);

    // ---- fused structure scores for this block's 32 rows (warp = 4 rows) ----
    {
        float w1[8], w2[8];
        #pragma unroll
        for (int e = 0; e < 8; e++) {
            w1[e] = g_vs1[lane + 32 * e];
            w2[e] = g_vs2[lane + 32 * e];
        }
        float bs1 = g_scal[2], bs2 = g_scal[3];
        #pragma unroll
        for (int r = 0; r < 4; r++) {
            int row = block_m + warp * 4 + r;
            const float* x = hstruct + (size_t)row * IN_F;
            float v[8];
            float m = -INFINITY;
            #pragma unroll
            for (int e = 0; e < 8; e++) { v[e] = x[lane + 32 * e]; m = fmaxf(m, v[e]); }
            m = warpMax(m);
            float z = 0.f, d1 = 0.f, d2 = 0.f;
            #pragma unroll
            for (int e = 0; e < 8; e++) {
                float ex = __expf(v[e] - m);
                z  += ex;
                d1 += ex * w1[e];
                d2 += ex * w2[e];
            }
            z  = warpSum(z);
            d1 = warpSum(d1);
            d2 = warpSum(d2);
            if (lane == 0) {
                g_ss_src[row] = d1 / z + bs1;
                g_sd[row].y   = d2 / z + bs2;
            }
        }
    }

    // ---- tensor-core mainloop ----
    int mrow = (warp >> 2) * 16;     // 0 or 16
    int nbase = (warp & 3) * 32;     // 0,32,64,96
    int g  = lane >> 2;              // 0..7
    int t4 = lane & 3;               // 0..3
    float acc[4][4] = {};

    #define CONV(buf_)                                                        \
        conv_sts(ra0, &A_s[buf_][0][arow][akc],      &A_s[buf_][1][arow][akc]);      \
        conv_sts(rw0, &W_s[buf_][0][arow][akc],      &W_s[buf_][1][arow][akc]);      \
        conv_sts(rw1, &W_s[buf_][0][arow + 32][akc], &W_s[buf_][1][arow + 32][akc]); \
        conv_sts(rw2, &W_s[buf_][0][arow + 64][akc], &W_s[buf_][1][arow + 64][akc]); \
        conv_sts(rw3, &W_s[buf_][0][arow + 96][akc], &W_s[buf_][1][arow + 96][akc]);

    CONV(0);
    __syncthreads();

    #pragma unroll 1
    for (int c = 0; c < KCHUNKS; c++) {
        int buf = c & 1;
        if (c < KCHUNKS - 1) { GLD((c + 1) * BK); }
        #pragma unroll
        for (int ks = 0; ks < 2; ks++) {
            int kb = ks * 16 + 2 * t4;
            unsigned ah[4], al[4];
            ah[0] = *(const unsigned*)&A_s[buf][0][mrow + g][kb];
            ah[1] = *(const unsigned*)&A_s[buf][0][mrow + g + 8][kb];
            ah[2] = *(const unsigned*)&A_s[buf][0][mrow + g][kb + 8];
            ah[3] = *(const unsigned*)&A_s[buf][0][mrow + g + 8][kb + 8];
            al[0] = *(const unsigned*)&A_s[buf][1][mrow + g][kb];
            al[1] = *(const unsigned*)&A_s[buf][1][mrow + g + 8][kb];
            al[2] = *(const unsigned*)&A_s[buf][1][mrow + g][kb + 8];
            al[3] = *(const unsigned*)&A_s[buf][1][mrow + g + 8][kb + 8];
            #pragma unroll
            for (int t = 0; t < 4; t++) {
                int n = nbase + 8 * t + g;
                unsigned bh0 = *(const unsigned*)&W_s[buf][0][n][kb];
                unsigned bh1 = *(const unsigned*)&W_s[buf][0][n][kb + 8];
                unsigned bl0 = *(const unsigned*)&W_s[buf][1][n][kb];
                unsigned bl1 = *(const unsigned*)&W_s[buf][1][n][kb + 8];
                mma_bf16(acc[t], ah, bh0, bh1);
                mma_bf16(acc[t], ah, bl0, bl1);
                mma_bf16(acc[t], al, bh0, bh1);
            }
        }
        if (c < KCHUNKS - 1) {
            CONV(buf ^ 1);
            __syncthreads();
        }
    }

    // epilogue: bias add, hc store, fused context scores
    float s1g = 0.f, s1h = 0.f, s2g = 0.f, s2h = 0.f;
    int row0 = block_m + mrow + g;
    #pragma unroll
    for (int t = 0; t < 4; t++) {
        int col = nbase + 8 * t + 2 * t4;
        float2 bb  = *(const float2*)&b[col];
        float2 w1v = *(const float2*)&ac_w[col];
        float2 w2v = *(const float2*)&ac_w[OUT_F + col];
        float c0 = acc[t][0] + bb.x;
        float c1 = acc[t][1] + bb.y;
        float c2 = acc[t][2] + bb.x;
        float c3 = acc[t][3] + bb.y;
        *(float2*)&g_hc[(size_t)row0 * OUT_F + col]       = make_float2(c0, c1);
        *(float2*)&g_hc[(size_t)(row0 + 8) * OUT_F + col] = make_float2(c2, c3);
        s1g += c0 * w1v.x + c1 * w1v.y;
        s1h += c2 * w1v.x + c3 * w1v.y;
        s2g += c0 * w2v.x + c1 * w2v.y;
        s2h += c2 * w2v.x + c3 * w2v.y;
    }
    #pragma unroll
    for (int o = 1; o <= 2; o <<= 1) {
        s1g += __shfl_xor_sync(0xffffffffu, s1g, o);
        s1h += __shfl_xor_sync(0xffffffffu, s1h, o);
        s2g += __shfl_xor_sync(0xffffffffu, s2g, o);
        s2h += __shfl_xor_sync(0xffffffffu, s2h, o);
    }
    if (t4 == 0) {
        p_s1[warp][g] = s1g;  p_s1[warp][g + 8] = s1h;
        p_s2[warp][g] = s2g;  p_s2[warp][g + 8] = s2h;
    }
    __syncthreads();
    if (tid < BM) {
        int mt = tid >> 4, r = tid & 15;
        int row = block_m + mt * 16 + r;
        float s1 = 0.f, s2 = 0.f;
        #pragma unroll
        for (int w = 0; w < 4; w++) {
            s1 += p_s1[mt * 4 + w][r];
            s2 += p_s2[mt * 4 + w][r];
        }
        g_sc_src[row] = s1;
        g_sd[row].x   = s2;
    }
}

// ---------------- warp-per-row sparse masked softmax + gather ----------------
// 8 warps/block, each warp owns one row: shuffle-only reductions, no
// __syncthreads. Bitmap rows are re-zeroed after last read; block 0 warp 0
// re-zeroes g_vs for the next replay.
__global__ void __launch_bounds__(256) k_attn(float* __restrict__ out,
                                              const float* __restrict__ Ws_coff,
                                              const float* __restrict__ Wc_coff) {
    __shared__ float wl[8][CAPW];
    __shared__ unsigned short jl[8][CAPW];

    int tid = threadIdx.x;
    int lane = tid & 31;
    int warp = tid >> 5;
    int row = blockIdx.x * 8 + warp;
    float ca = fabsf(Ws_coff[0]);   // multiplies alpha_c (per reference)
    float cs = fabsf(Wc_coff[0]);   // multiplies alpha_s
    float sci = g_sc_src[row], ssi = g_ss_src[row];

    if (blockIdx.x == 0 && warp == 0) {
        #pragma unroll
        for (int i = 0; i < 8; i++) {
            g_vs1[lane + 32 * i] = 0.f;
            g_vs2[lane + 32 * i] = 0.f;
        }
    }

    // load this row's 256 bitmap words: 8 per lane as two uint4
    unsigned* adjrow = &g_adj[row * NWORDS];
    uint4 wa = *(const uint4*)&adjrow[lane * 4];
    uint4 wb = *(const uint4*)&adjrow[128 + lane * 4];
    unsigned ws[8] = {wa.x, wa.y, wa.z, wa.w, wb.x, wb.y, wb.z, wb.w};
    int cnt = 0;
    #pragma unroll
    for (int i = 0; i < 8; i++) cnt += __popc(ws[i]);

    // exclusive prefix over lanes
    int inc = cnt;
    #pragma unroll
    for (int o = 1; o < 32; o <<= 1) {
        int v = __shfl_up_sync(0xffffffffu, inc, o);
        if (lane >= o) inc += v;
    }
    int total = __shfl_sync(0xffffffffu, inc, 31);
    int off = inc - cnt;

    // reset bitmap for next replay (conditional: most segments are zero)
    if (wa.x | wa.y | wa.z | wa.w)
        *(uint4*)&adjrow[lane * 4] = make_uint4(0u, 0u, 0u, 0u);
    if (wb.x | wb.y | wb.z | wb.w)
        *(uint4*)&adjrow[128 + lane * 4] = make_uint4(0u, 0u, 0u, 0u);

    if (total == 0) {
        // masked row == all -9e15 -> uniform softmax -> mean of hc
        float4 acc = make_float4(0.f, 0.f, 0.f, 0.f);
        for (int j = 0; j < Nn; j++) {
            float4 h = *(const float4*)&g_hc[(size_t)j * OUT_F + lane * 4];
            acc.x += h.x; acc.y += h.y; acc.z += h.z; acc.w += h.w;
        }
        float s = 1.f / (float)Nn;
        acc.x *= s; acc.y *= s; acc.z *= s; acc.w *= s;
        *(float4*)&out[(size_t)row * OUT_F + lane * 4] = acc;
        return;
    }

    float m = -INFINITY;
    float inv;
    if (total <= CAPW) {
        // single pass: alpha -> list, track max
        int o = off;
        #pragma unroll
        for (int i = 0; i < 8; i++) {
            unsigned w = ws[i];
            int base = ((i < 4) ? (lane * 4 + i) : (128 + lane * 4 + (i - 4))) * 32;
            while (w) {
                int bpos = __ffs(w) - 1; w &= w - 1;
                int j = base + bpos;
                float2 sd = g_sd[j];
                float a = ca * lrelu(sci + sd.x) + cs * lrelu(ssi + sd.y);
                m = fmaxf(m, a);
                wl[warp][o] = a;
                jl[warp][o] = (unsigned short)j;
                o++;
            }
        }
        m = warpMax(m);
        __syncwarp();
        float zloc = 0.f;
        for (int k = lane; k < total; k += 32) {
            float e = __expf(wl[warp][k] - m);
            wl[warp][k] = e;
            zloc += e;
        }
        inv = 1.f / warpSum(zloc);
        __syncwarp();
        // gather: all 32 lanes cooperate per edge (float4 features)
        float4 acc = make_float4(0.f, 0.f, 0.f, 0.f);
        int k = 0;
        for (; k + 2 <= total; k += 2) {
            float w0 = wl[warp][k],     w1 = wl[warp][k + 1];
            int   j0 = jl[warp][k],     j1 = jl[warp][k + 1];
            float4 h0 = *(const float4*)&g_hc[(size_t)j0 * OUT_F + lane * 4];
            float4 h1 = *(const float4*)&g_hc[(size_t)j1 * OUT_F + lane * 4];
            acc.x += w0 * h0.x + w1 * h1.x;
            acc.y += w0 * h0.y + w1 * h1.y;
            acc.z += w0 * h0.z + w1 * h1.z;
            acc.w += w0 * h0.w + w1 * h1.w;
        }
        if (k < total) {
            float w0 = wl[warp][k];
            float4 h0 = *(const float4*)&g_hc[(size_t)jl[warp][k] * OUT_F + lane * 4];
            acc.x += w0 * h0.x; acc.y += w0 * h0.y;
            acc.z += w0 * h0.z; acc.w += w0 * h0.w;
        }
        acc.x *= inv; acc.y *= inv; acc.z *= inv; acc.w *= inv;
        *(float4*)&out[(size_t)row * OUT_F + lane * 4] = acc;
        return;
    }

    // slow path (degree > CAPW): max pass, Z pass, then chunked gather
    #pragma unroll
    for (int i = 0; i < 8; i++) {
        unsigned w = ws[i];
        int base = ((i < 4) ? (lane * 4 + i) : (128 + lane * 4 + (i - 4))) * 32;
        while (w) {
            int bpos = __ffs(w) - 1; w &= w - 1;
            float2 sd = g_sd[base + bpos];
            m = fmaxf(m, ca * lrelu(sci + sd.x) + cs * lrelu(ssi + sd.y));
        }
    }
    m = warpMax(m);
    {
        float zloc = 0.f;
        #pragma unroll
        for (int i = 0; i < 8; i++) {
            unsigned w = ws[i];
            int base = ((i < 4) ? (lane * 4 + i) : (128 + lane * 4 + (i - 4))) * 32;
            while (w) {
                int bpos = __ffs(w) - 1; w &= w - 1;
                float2 sd = g_sd[base + bpos];
                zloc += __expf(ca * lrelu(sci + sd.x) + cs * lrelu(ssi + sd.y) - m);
            }
        }
        inv = 1.f / warpSum(zloc);
    }
    float4 acc = make_float4(0.f, 0.f, 0.f, 0.f);
    for (int c0 = 0; c0 < total; c0 += CAPW) {
        __syncwarp();
        int o = off;
        #pragma unroll
        for (int i = 0; i < 8; i++) {
            unsigned w = ws[i];
            int base = ((i < 4) ? (lane * 4 + i) : (128 + lane * 4 + (i - 4))) * 32;
            while (w) {
                int bpos = __ffs(w) - 1; w &= w - 1;
                if (o >= c0 && o < c0 + CAPW) {
                    int j = base + bpos;
                    float2 sd = g_sd[j];
                    wl[warp][o - c0] = __expf(ca * lrelu(sci + sd.x) + cs * lrelu(ssi + sd.y) - m);
                    jl[warp][o - c0] = (unsigned short)j;
                }
                o++;
            }
        }
        __syncwarp();
        int cc = total - c0 < CAPW ? total - c0 : CAPW;
        for (int k = 0; k < cc; k++) {
            float wv = wl[warp][k];
            float4 h = *(const float4*)&g_hc[(size_t)jl[warp][k] * OUT_F + lane * 4];
            acc.x += wv * h.x; acc.y += wv * h.y;
            acc.z += wv * h.z; acc.w += wv * h.w;
        }
    }
    acc.x *= inv; acc.y *= inv; acc.z *= inv; acc.w *= inv;
    *(float4*)&out[(size_t)row * OUT_F + lane * 4] = acc;
}

// ---------------- launch ----------------
extern "C" void kernel_launch(void* const* d_in, const int* in_sizes, int n_in,
                              void* d_out, int out_size) {
    const float* h_context   = (const float*)d_in[0];
    const float* h_structure = (const float*)d_in[1];
    const int*   edge        = (const int*)d_in[2];   // int32 or int64, detected per block
    const float* Wc_w        = (const float*)d_in[3];
    const float* Wc_b        = (const float*)d_in[4];
    const float* Ws_w        = (const float*)d_in[5];
    const float* Ws_b        = (const float*)d_in[6];
    const float* ac_w        = (const float*)d_in[7];
    const float* as_w        = (const float*)d_in[8];
    const float* Ws_coff     = (const float*)d_in[9];
    const float* Wc_coff     = (const float*)d_in[10];
    float* out = (float*)d_out;
    int E = in_sizes[2] / 2;

    k_edges<<<(E + 255) / 256, 256>>>(edge, E, Ws_w, Ws_b, as_w, Ws_coff, Wc_coff);
    k_gemm<<<Nn / BM, 256>>>(h_context, Wc_w, Wc_b, ac_w, h_structure);
    k_attn<<<Nn / 8, 256>>>(out, Ws_coff, Wc_coff);
}

// round 14
// speedup vs baseline: 1.0576x; 1.0576x over previous
#include <cuda_runtime.h>
#include <cuda_bf16.h>
#include <cuda_fp16.h>
#include <math.h>

#define Nn 8192
#define IN_F 256
#define OUT_F 128
#define NWORDS 256   // bitmap words per row (8192 bits)
#define CAPW 256     // per-warp neighbor list capacity (expected degree ~32)

// ---------------- device scratch (no allocs allowed) ----------------
// g_adj and g_vs start zeroed (static init) and are re-zeroed by k_attn
// after use, so every replay starts from a clean state.
__device__ __half   g_hch[Nn * OUT_F];         // 2 MB (fp16 hc for the gather)
__device__ unsigned g_adj[Nn * NWORDS];        // 8 MB adjacency bitmap
__device__ float    g_sc_src[Nn];
__device__ float    g_ss_src[Nn];
__device__ float2   g_sd[Nn];                  // (sc_dst, ss_dst) packed
__device__ float    g_vs1[IN_F], g_vs2[IN_F];  // hs-GEMM fold vectors
__device__ float    g_scal[4];                 // ca, cs, bs1, bs2

__device__ __forceinline__ float lrelu(float x) { return x > 0.f ? x : 0.01f * x; }

__device__ __forceinline__ float warpMax(float v) {
    #pragma unroll
    for (int o = 16; o; o >>= 1) v = fmaxf(v, __shfl_xor_sync(0xffffffffu, v, o));
    return v;
}
__device__ __forceinline__ float warpSum(float v) {
    #pragma unroll
    for (int o = 16; o; o >>= 1) v += __shfl_xor_sync(0xffffffffu, v, o);
    return v;
}

// ---------------- kernels ----------------
// Edge bitmap build: all 4 candidate loads hoisted (MLP=4); per-WARP i32/i64
// detection via __any_sync (no block barrier). Blocks 0..7 also accumulate
// the hs-GEMM fold into g_vs; block 8 does bias dots + coefficient abs.
__global__ void k_edges(const int* __restrict__ p32, int E,
                        const float* __restrict__ Ws_w,
                        const float* __restrict__ Ws_b,
                        const float* __restrict__ as_w,
                        const float* __restrict__ Ws_coff,
                        const float* __restrict__ Wc_coff) {
    int tid = threadIdx.x;
    int e = blockIdx.x * blockDim.x + tid;
    const long long* p64 = (const long long*)p32;

    unsigned long long vr = 0ull, vc = 0ull;
    int r32 = 0, c32 = 0;
    if (e < E) {
        vr  = (unsigned long long)p64[e];       // i64 row candidate
        vc  = (unsigned long long)p64[E + e];   // i64 col candidate
        r32 = p32[e];                           // i32 row candidate
        c32 = p32[E + e];                       // i32 col candidate
    }
    // int64 little-endian ids < 8192 -> high words all zero. A warp sees 64
    // id values; all-zero under i32 is impossible on real data.
    int isi32 = __any_sync(0xffffffffu, (((vr | vc) >> 32) != 0ull));
    if (e < E) {
        int r = isi32 ? r32 : (int)(unsigned)vr;
        int c = isi32 ? c32 : (int)(unsigned)vc;
        if ((unsigned)r < Nn && (unsigned)c < Nn)
            atomicOr(&g_adj[r * NWORDS + (c >> 5)], 1u << (c & 31));
    }
    if (blockIdx.x < 8) {
        float v1 = 0.f, v2 = 0.f;
        #pragma unroll
        for (int i = 0; i < 16; i++) {
            int f = blockIdx.x * 16 + i;
            float w = Ws_w[f * IN_F + tid];
            v1 += w * as_w[f];
            v2 += w * as_w[OUT_F + f];
        }
        atomicAdd(&g_vs1[tid], v1);
        atomicAdd(&g_vs2[tid], v2);
    } else if (blockIdx.x == 8 && tid < 32) {
        float b1 = 0.f, b2 = 0.f;
        #pragma unroll
        for (int i = 0; i < 4; i++) {
            int f = tid + 32 * i;
            float wb = Ws_b[f];
            b1 += wb * as_w[f];
            b2 += wb * as_w[OUT_F + f];
        }
        b1 = warpSum(b1);
        b2 = warpSum(b2);
        if (tid == 0) {
            g_scal[0] = fabsf(Ws_coff[0]);  // multiplies alpha_c
            g_scal[1] = fabsf(Wc_coff[0]);  // multiplies alpha_s
            g_scal[2] = b1;
            g_scal[3] = b2;
        }
    }
}

// ---------------- split-bf16 tensor-core GEMM + fused structure scores -----
// hc = h_context @ Wc_w^T + Wc_b via mma.sync m16n8k16 bf16:
//   a*b ~= a_hi*b_hi + a_hi*b_lo + a_lo*b_hi   (fp32 accumulate)
// Epilogue stores hc as fp16 (g_hch) — the only consumer is the weighted
// gather, where fp16 rel-err (~5e-4) is well under the 1e-3 budget.
#define BM 32
#define BK 32
#define KCHUNKS (IN_F / BK)
#define APAD 40

__device__ __forceinline__ void mma_bf16(float* c, const unsigned* a,
                                         unsigned b0, unsigned b1) {
    asm volatile(
        "mma.sync.aligned.m16n8k16.row.col.f32.bf16.bf16.f32 "
        "{%0,%1,%2,%3}, {%4,%5,%6,%7}, {%8,%9}, {%0,%1,%2,%3};"
        : "+f"(c[0]), "+f"(c[1]), "+f"(c[2]), "+f"(c[3])
        : "r"(a[0]), "r"(a[1]), "r"(a[2]), "r"(a[3]), "r"(b0), "r"(b1));
}

__device__ __forceinline__ unsigned pk2(float x, float y) {
    unsigned r;
    asm("cvt.rn.bf16x2.f32 %0, %1, %2;" : "=r"(r) : "f"(y), "f"(x));
    return r;
}
__device__ __forceinline__ float bflo(unsigned u) { return __uint_as_float(u << 16); }
__device__ __forceinline__ float bfhi(unsigned u) { return __uint_as_float(u & 0xffff0000u); }

__device__ __forceinline__ void conv_sts(float4 v, __nv_bfloat16* hip, __nv_bfloat16* lop) {
    unsigned h0 = pk2(v.x, v.y);
    unsigned h1 = pk2(v.z, v.w);
    unsigned l0 = pk2(v.x - bflo(h0), v.y - bfhi(h0));
    unsigned l1 = pk2(v.z - bflo(h1), v.w - bfhi(h1));
    *(uint2*)hip = make_uint2(h0, h1);
    *(uint2*)lop = make_uint2(l0, l1);
}

__global__ void __launch_bounds__(256, 2) k_gemm(const float* __restrict__ A,
                                                 const float* __restrict__ W,
                                                 const float* __restrict__ b,
                                                 const float* __restrict__ ac_w,
                                                 const float* __restrict__ hstruct) {
    __shared__ __align__(16) __nv_bfloat16 A_s[2][2][BM][APAD];
    __shared__ __align__(16) __nv_bfloat16 W_s[2][2][OUT_F][APAD];
    __shared__ float p_s1[8][16], p_s2[8][16];

    int tid = threadIdx.x;
    int lane = tid & 31;
    int warp = tid >> 5;
    int block_m = blockIdx.x * BM;

    int arow = tid >> 3;             // 0..31
    int akc  = (tid & 7) * 4;

    float4 ra0, rw0, rw1, rw2, rw3;
    #define GLD(c0_)                                                          \
        ra0 = *(const float4*)&A[(size_t)(block_m + arow) * IN_F + (c0_) + akc];      \
        rw0 = *(const float4*)&W[(size_t)arow * IN_F + (c0_) + akc];                  \
        rw1 = *(const float4*)&W[(size_t)(arow + 32) * IN_F + (c0_) + akc];           \
        rw2 = *(const float4*)&W[(size_t)(arow + 64) * IN_F + (c0_) + akc];           \
        rw3 = *(const float4*)&W[(size_t)(arow + 96) * IN_F + (c0_) + akc];

    // prefetch first GEMM tile before the sscore prologue
    GLD(0);

    // ---- fused structure scores for this block's 32 rows (warp = 4 rows) ----
    {
        float w1[8], w2[8];
        #pragma unroll
        for (int e = 0; e < 8; e++) {
            w1[e] = g_vs1[lane + 32 * e];
            w2[e] = g_vs2[lane + 32 * e];
        }
        float bs1 = g_scal[2], bs2 = g_scal[3];
        #pragma unroll
        for (int r = 0; r < 4; r++) {
            int row = block_m + warp * 4 + r;
            const float* x = hstruct + (size_t)row * IN_F;
            float v[8];
            float m = -INFINITY;
            #pragma unroll
            for (int e = 0; e < 8; e++) { v[e] = x[lane + 32 * e]; m = fmaxf(m, v[e]); }
            m = warpMax(m);
            float z = 0.f, d1 = 0.f, d2 = 0.f;
            #pragma unroll
            for (int e = 0; e < 8; e++) {
                float ex = __expf(v[e] - m);
                z  += ex;
                d1 += ex * w1[e];
                d2 += ex * w2[e];
            }
            z  = warpSum(z);
            d1 = warpSum(d1);
            d2 = warpSum(d2);
            if (lane == 0) {
                g_ss_src[row] = d1 / z + bs1;
                g_sd[row].y   = d2 / z + bs2;
            }
        }
    }

    // ---- tensor-core mainloop ----
    int mrow = (warp >> 2) * 16;     // 0 or 16
    int nbase = (warp & 3) * 32;     // 0,32,64,96
    int g  = lane >> 2;              // 0..7
    int t4 = lane & 3;               // 0..3
    float acc[4][4] = {};

    #define CONV(buf_)                                                        \
        conv_sts(ra0, &A_s[buf_][0][arow][akc],      &A_s[buf_][1][arow][akc]);      \
        conv_sts(rw0, &W_s[buf_][0][arow][akc],      &W_s[buf_][1][arow][akc]);      \
        conv_sts(rw1, &W_s[buf_][0][arow + 32][akc], &W_s[buf_][1][arow + 32][akc]); \
        conv_sts(rw2, &W_s[buf_][0][arow + 64][akc], &W_s[buf_][1][arow + 64][akc]); \
        conv_sts(rw3, &W_s[buf_][0][arow + 96][akc], &W_s[buf_][1][arow + 96][akc]);

    CONV(0);
    __syncthreads();

    #pragma unroll 1
    for (int c = 0; c < KCHUNKS; c++) {
        int buf = c & 1;
        if (c < KCHUNKS - 1) { GLD((c + 1) * BK); }
        #pragma unroll
        for (int ks = 0; ks < 2; ks++) {
            int kb = ks * 16 + 2 * t4;
            unsigned ah[4], al[4];
            ah[0] = *(const unsigned*)&A_s[buf][0][mrow + g][kb];
            ah[1] = *(const unsigned*)&A_s[buf][0][mrow + g + 8][kb];
            ah[2] = *(const unsigned*)&A_s[buf][0][mrow + g][kb + 8];
            ah[3] = *(const unsigned*)&A_s[buf][0][mrow + g + 8][kb + 8];
            al[0] = *(const unsigned*)&A_s[buf][1][mrow + g][kb];
            al[1] = *(const unsigned*)&A_s[buf][1][mrow + g + 8][kb];
            al[2] = *(const unsigned*)&A_s[buf][1][mrow + g][kb + 8];
            al[3] = *(const unsigned*)&A_s[buf][1][mrow + g + 8][kb + 8];
            #pragma unroll
            for (int t = 0; t < 4; t++) {
                int n = nbase + 8 * t + g;
                unsigned bh0 = *(const unsigned*)&W_s[buf][0][n][kb];
                unsigned bh1 = *(const unsigned*)&W_s[buf][0][n][kb + 8];
                unsigned bl0 = *(const unsigned*)&W_s[buf][1][n][kb];
                unsigned bl1 = *(const unsigned*)&W_s[buf][1][n][kb + 8];
                mma_bf16(acc[t], ah, bh0, bh1);
                mma_bf16(acc[t], ah, bl0, bl1);
                mma_bf16(acc[t], al, bh0, bh1);
            }
        }
        if (c < KCHUNKS - 1) {
            CONV(buf ^ 1);
            __syncthreads();
        }
    }

    // epilogue: bias add, fp16 hc store, fused context scores
    float s1g = 0.f, s1h = 0.f, s2g = 0.f, s2h = 0.f;
    int row0 = block_m + mrow + g;
    #pragma unroll
    for (int t = 0; t < 4; t++) {
        int col = nbase + 8 * t + 2 * t4;
        float2 bb  = *(const float2*)&b[col];
        float2 w1v = *(const float2*)&ac_w[col];
        float2 w2v = *(const float2*)&ac_w[OUT_F + col];
        float c0 = acc[t][0] + bb.x;
        float c1 = acc[t][1] + bb.y;
        float c2 = acc[t][2] + bb.x;
        float c3 = acc[t][3] + bb.y;
        *(__half2*)&g_hch[(size_t)row0 * OUT_F + col]       = __floats2half2_rn(c0, c1);
        *(__half2*)&g_hch[(size_t)(row0 + 8) * OUT_F + col] = __floats2half2_rn(c2, c3);
        s1g += c0 * w1v.x + c1 * w1v.y;
        s1h += c2 * w1v.x + c3 * w1v.y;
        s2g += c0 * w2v.x + c1 * w2v.y;
        s2h += c2 * w2v.x + c3 * w2v.y;
    }
    #pragma unroll
    for (int o = 1; o <= 2; o <<= 1) {
        s1g += __shfl_xor_sync(0xffffffffu, s1g, o);
        s1h += __shfl_xor_sync(0xffffffffu, s1h, o);
        s2g += __shfl_xor_sync(0xffffffffu, s2g, o);
        s2h += __shfl_xor_sync(0xffffffffu, s2h, o);
    }
    if (t4 == 0) {
        p_s1[warp][g] = s1g;  p_s1[warp][g + 8] = s1h;
        p_s2[warp][g] = s2g;  p_s2[warp][g + 8] = s2h;
    }
    __syncthreads();
    if (tid < BM) {
        int mt = tid >> 4, r = tid & 15;
        int row = block_m + mt * 16 + r;
        float s1 = 0.f, s2 = 0.f;
        #pragma unroll
        for (int w = 0; w < 4; w++) {
            s1 += p_s1[mt * 4 + w][r];
            s2 += p_s2[mt * 4 + w][r];
        }
        g_sc_src[row] = s1;
        g_sd[row].x   = s2;
    }
}

// ---------------- warp-per-row sparse masked softmax + fp16 gather ----------
// 8 warps/block, each warp owns one row: shuffle-only reductions, no
// __syncthreads. Per-edge gather is 256 B (fp16 row) instead of 512 B.
__global__ void __launch_bounds__(256) k_attn(float* __restrict__ out,
                                              const float* __restrict__ Ws_coff,
                                              const float* __restrict__ Wc_coff) {
    __shared__ float wl[8][CAPW];
    __shared__ unsigned short jl[8][CAPW];

    int tid = threadIdx.x;
    int lane = tid & 31;
    int warp = tid >> 5;
    int row = blockIdx.x * 8 + warp;
    float ca = fabsf(Ws_coff[0]);   // multiplies alpha_c (per reference)
    float cs = fabsf(Wc_coff[0]);   // multiplies alpha_s
    float sci = g_sc_src[row], ssi = g_ss_src[row];

    if (blockIdx.x == 0 && warp == 0) {
        #pragma unroll
        for (int i = 0; i < 8; i++) {
            g_vs1[lane + 32 * i] = 0.f;
            g_vs2[lane + 32 * i] = 0.f;
        }
    }

    // load this row's 256 bitmap words: 8 per lane as two uint4
    unsigned* adjrow = &g_adj[row * NWORDS];
    uint4 wa = *(const uint4*)&adjrow[lane * 4];
    uint4 wb = *(const uint4*)&adjrow[128 + lane * 4];
    unsigned ws[8] = {wa.x, wa.y, wa.z, wa.w, wb.x, wb.y, wb.z, wb.w};
    int cnt = 0;
    #pragma unroll
    for (int i = 0; i < 8; i++) cnt += __popc(ws[i]);

    // exclusive prefix over lanes
    int inc = cnt;
    #pragma unroll
    for (int o = 1; o < 32; o <<= 1) {
        int v = __shfl_up_sync(0xffffffffu, inc, o);
        if (lane >= o) inc += v;
    }
    int total = __shfl_sync(0xffffffffu, inc, 31);
    int off = inc - cnt;

    // reset bitmap for next replay (conditional: most segments are zero)
    if (wa.x | wa.y | wa.z | wa.w)
        *(uint4*)&adjrow[lane * 4] = make_uint4(0u, 0u, 0u, 0u);
    if (wb.x | wb.y | wb.z | wb.w)
        *(uint4*)&adjrow[128 + lane * 4] = make_uint4(0u, 0u, 0u, 0u);

    if (total == 0) {
        // masked row == all -9e15 -> uniform softmax -> mean of hc
        float4 acc = make_float4(0.f, 0.f, 0.f, 0.f);
        for (int j = 0; j < Nn; j++) {
            const __half2* hp = (const __half2*)&g_hch[(size_t)j * OUT_F + lane * 4];
            float2 f0 = __half22float2(hp[0]);
            float2 f1 = __half22float2(hp[1]);
            acc.x += f0.x; acc.y += f0.y; acc.z += f1.x; acc.w += f1.y;
        }
        float s = 1.f / (float)Nn;
        acc.x *= s; acc.y *= s; acc.z *= s; acc.w *= s;
        *(float4*)&out[(size_t)row * OUT_F + lane * 4] = acc;
        return;
    }

    float m = -INFINITY;
    float inv;
    if (total <= CAPW) {
        // single pass: alpha -> list, track max
        int o = off;
        #pragma unroll
        for (int i = 0; i < 8; i++) {
            unsigned w = ws[i];
            int base = ((i < 4) ? (lane * 4 + i) : (128 + lane * 4 + (i - 4))) * 32;
            while (w) {
                int bpos = __ffs(w) - 1; w &= w - 1;
                int j = base + bpos;
                float2 sd = g_sd[j];
                float a = ca * lrelu(sci + sd.x) + cs * lrelu(ssi + sd.y);
                m = fmaxf(m, a);
                wl[warp][o] = a;
                jl[warp][o] = (unsigned short)j;
                o++;
            }
        }
        m = warpMax(m);
        __syncwarp();
        float zloc = 0.f;
        for (int k = lane; k < total; k += 32) {
            float e = __expf(wl[warp][k] - m);
            wl[warp][k] = e;
            zloc += e;
        }
        inv = 1.f / warpSum(zloc);
        __syncwarp();
        // gather: all 32 lanes cooperate per edge (4 fp16 features / lane)
        float4 acc = make_float4(0.f, 0.f, 0.f, 0.f);
        int k = 0;
        for (; k + 2 <= total; k += 2) {
            float w0 = wl[warp][k],     w1 = wl[warp][k + 1];
            int   j0 = jl[warp][k],     j1 = jl[warp][k + 1];
            const __half2* h0 = (const __half2*)&g_hch[(size_t)j0 * OUT_F + lane * 4];
            const __half2* h1 = (const __half2*)&g_hch[(size_t)j1 * OUT_F + lane * 4];
            __half2 a0 = h0[0], a1 = h0[1], b0 = h1[0], b1 = h1[1];
            float2 fa0 = __half22float2(a0), fa1 = __half22float2(a1);
            float2 fb0 = __half22float2(b0), fb1 = __half22float2(b1);
            acc.x += w0 * fa0.x + w1 * fb0.x;
            acc.y += w0 * fa0.y + w1 * fb0.y;
            acc.z += w0 * fa1.x + w1 * fb1.x;
            acc.w += w0 * fa1.y + w1 * fb1.y;
        }
        if (k < total) {
            float w0 = wl[warp][k];
            const __half2* h0 = (const __half2*)&g_hch[(size_t)jl[warp][k] * OUT_F + lane * 4];
            float2 fa0 = __half22float2(h0[0]), fa1 = __half22float2(h0[1]);
            acc.x += w0 * fa0.x; acc.y += w0 * fa0.y;
            acc.z += w0 * fa1.x; acc.w += w0 * fa1.y;
        }
        acc.x *= inv; acc.y *= inv; acc.z *= inv; acc.w *= inv;
        *(float4*)&out[(size_t)row * OUT_F + lane * 4] = acc;
        return;
    }

    // slow path (degree > CAPW): max pass, Z pass, then chunked gather
    #pragma unroll
    for (int i = 0; i < 8; i++) {
        unsigned w = ws[i];
        int base = ((i < 4) ? (lane * 4 + i) : (128 + lane * 4 + (i - 4))) * 32;
        while (w) {
            int bpos = __ffs(w) - 1; w &= w - 1;
            float2 sd = g_sd[base + bpos];
            m = fmaxf(m, ca * lrelu(sci + sd.x) + cs * lrelu(ssi + sd.y));
        }
    }
    m = warpMax(m);
    {
        float zloc = 0.f;
        #pragma unroll
        for (int i = 0; i < 8; i++) {
            unsigned w = ws[i];
            int base = ((i < 4) ? (lane * 4 + i) : (128 + lane * 4 + (i - 4))) * 32;
            while (w) {
                int bpos = __ffs(w) - 1; w &= w - 1;
                float2 sd = g_sd[base + bpos];
                zloc += __expf(ca * lrelu(sci + sd.x) + cs * lrelu(ssi + sd.y) - m);
            }
        }
        inv = 1.f / warpSum(zloc);
    }
    float4 acc = make_float4(0.f, 0.f, 0.f, 0.f);
    for (int c0 = 0; c0 < total; c0 += CAPW) {
        __syncwarp();
        int o = off;
        #pragma unroll
        for (int i = 0; i < 8; i++) {
            unsigned w = ws[i];
            int base = ((i < 4) ? (lane * 4 + i) : (128 + lane * 4 + (i - 4))) * 32;
            while (w) {
                int bpos = __ffs(w) - 1; w &= w - 1;
                if (o >= c0 && o < c0 + CAPW) {
                    int j = base + bpos;
                    float2 sd = g_sd[j];
                    wl[warp][o - c0] = __expf(ca * lrelu(sci + sd.x) + cs * lrelu(ssi + sd.y) - m);
                    jl[warp][o - c0] = (unsigned short)j;
                }
                o++;
            }
        }
        __syncwarp();
        int cc = total - c0 < CAPW ? total - c0 : CAPW;
        for (int k = 0; k < cc; k++) {
            float wv = wl[warp][k];
            const __half2* hp = (const __half2*)&g_hch[(size_t)jl[warp][k] * OUT_F + lane * 4];
            float2 f0 = __half22float2(hp[0]), f1 = __half22float2(hp[1]);
            acc.x += wv * f0.x; acc.y += wv * f0.y;
            acc.z += wv * f1.x; acc.w += wv * f1.y;
        }
    }
    acc.x *= inv; acc.y *= inv; acc.z *= inv; acc.w *= inv;
    *(float4*)&out[(size_t)row * OUT_F + lane * 4] = acc;
}

// ---------------- launch ----------------
extern "C" void kernel_launch(void* const* d_in, const int* in_sizes, int n_in,
                              void* d_out, int out_size) {
    const float* h_context   = (const float*)d_in[0];
    const float* h_structure = (const float*)d_in[1];
    const int*   edge        = (const int*)d_in[2];   // int32 or int64, detected per warp
    const float* Wc_w        = (const float*)d_in[3];
    const float* Wc_b        = (const float*)d_in[4];
    const float* Ws_w        = (const float*)d_in[5];
    const float* Ws_b        = (const float*)d_in[6];
    const float* ac_w        = (const float*)d_in[7];
    const float* as_w        = (const float*)d_in[8];
    const float* Ws_coff     = (const float*)d_in[9];
    const float* Wc_coff     = (const float*)d_in[10];
    float* out = (float*)d_out;
    int E = in_sizes[2] / 2;

    k_edges<<<(E + 255) / 256, 256>>>(edge, E, Ws_w, Ws_b, as_w, Ws_coff, Wc_coff);
    k_gemm<<<Nn / BM, 256>>>(h_context, Wc_w, Wc_b, ac_w, h_structure);
    k_attn<<<Nn / 8, 256>>>(out, Ws_coff, Wc_coff);
}